// round 1
// baseline (speedup 1.0000x reference)
#include <cuda_runtime.h>
#include <cstdint>
#include <math.h>

// Problem constants
constexpr int Tn  = 2048;   // tokens
constexpr int Hn  = 2048;   // hidden
constexpr int In  = 1024;   // moe intermediate
constexpr int En  = 8;      // experts
constexpr int ISn = 2048;   // shared intermediate
constexpr int Rn  = 4096;   // routed rows = T * topk

// ------------------------- scratch (device globals; no allocs) -------------
__device__ float g_buf[(size_t)Rn * 2048];   // 32MB: D-out [4096][2048] then G-out [2048][4096]
__device__ float g_hr [(size_t)Rn * In];     // 16MB: routed swiglu (weight folded), grouped rows
__device__ float g_yr [(size_t)Rn * Hn];     // 32MB: routed down output per grouped row
__device__ float g_hs [(size_t)Tn * ISn];    // 16MB: shared swiglu
__device__ int   g_tok[Rn];                  // token id per grouped row
__device__ float g_w  [Rn];                  // combine weight per grouped row
__device__ int   g_slot[Rn];                 // (t,k) -> grouped row
__device__ int   g_topk_i[Rn];
__device__ float g_topk_w[Rn];
__device__ int   g_cnt[En], g_off[En], g_cnt2[En];

// ------------------------- small helpers -----------------------------------
__device__ __forceinline__ uint32_t f2tf(float f) {
    uint32_t u;
    asm("cvt.rna.tf32.f32 %0, %1;" : "=r"(u) : "f"(f));
    return u;
}

__device__ __forceinline__ void mma8(float* c, const uint32_t* a, const uint32_t* b) {
    asm volatile(
        "mma.sync.aligned.m16n8k8.row.col.f32.tf32.tf32.f32 "
        "{%0,%1,%2,%3},{%4,%5,%6,%7},{%8,%9},{%0,%1,%2,%3};"
        : "+f"(c[0]), "+f"(c[1]), "+f"(c[2]), "+f"(c[3])
        : "r"(a[0]), "r"(a[1]), "r"(a[2]), "r"(a[3]), "r"(b[0]), "r"(b[1]));
}

__device__ __forceinline__ void ldsm4(uint32_t* d, uint32_t saddr) {
    asm volatile("ldmatrix.sync.aligned.m8n8.x4.shared.b16 {%0,%1,%2,%3},[%4];"
                 : "=r"(d[0]), "=r"(d[1]), "=r"(d[2]), "=r"(d[3]) : "r"(saddr));
}

// ------------------------- gate + routing -----------------------------------
__global__ void k_zero() {
    if (threadIdx.x < En) g_cnt[threadIdx.x] = 0;
}

__global__ void k_gate(const float* __restrict__ x, const float* __restrict__ gw) {
    int warp = threadIdx.x >> 5, lane = threadIdx.x & 31;
    int t = blockIdx.x * 8 + warp;
    float acc[En];
#pragma unroll
    for (int e = 0; e < En; ++e) acc[e] = 0.f;

    const float4* xr = reinterpret_cast<const float4*>(x + (size_t)t * Hn);
#pragma unroll 4
    for (int it = 0; it < Hn / 128; ++it) {
        float4 xv = xr[lane + 32 * it];
#pragma unroll
        for (int e = 0; e < En; ++e) {
            float4 wv = reinterpret_cast<const float4*>(gw + (size_t)e * Hn)[lane + 32 * it];
            acc[e] += xv.x * wv.x + xv.y * wv.y + xv.z * wv.z + xv.w * wv.w;
        }
    }
#pragma unroll
    for (int e = 0; e < En; ++e)
#pragma unroll
        for (int o = 16; o; o >>= 1) acc[e] += __shfl_xor_sync(0xffffffffu, acc[e], o);

    if (lane == 0) {
        int i0 = 0; float l0 = acc[0];
#pragma unroll
        for (int e = 1; e < En; ++e) if (acc[e] > l0) { l0 = acc[e]; i0 = e; }
        int i1 = -1; float l1 = -1e30f;
#pragma unroll
        for (int e = 0; e < En; ++e) if (e != i0 && acc[e] > l1) { l1 = acc[e]; i1 = e; }
        // renormalized top-2 softmax weights == pairwise sigmoid (exact)
        float e1 = expf(l1 - l0);
        float w0 = 1.f / (1.f + e1);
        float w1 = e1 / (1.f + e1);
        g_topk_i[2 * t]     = i0; g_topk_w[2 * t]     = w0;
        g_topk_i[2 * t + 1] = i1; g_topk_w[2 * t + 1] = w1;
        atomicAdd(&g_cnt[i0], 1);
        atomicAdd(&g_cnt[i1], 1);
    }
}

__global__ void k_offsets() {
    if (threadIdx.x == 0) {
        int s = 0;
        for (int e = 0; e < En; ++e) { g_off[e] = s; s += g_cnt[e]; }
    }
    if (threadIdx.x < En) g_cnt2[threadIdx.x] = 0;
}

__global__ void k_assign() {
    int idx = blockIdx.x * 256 + threadIdx.x;   // < Rn
    int e = g_topk_i[idx];
    int pos = g_off[e] + atomicAdd(&g_cnt2[e], 1);
    g_tok[pos] = idx >> 1;
    g_w[pos]   = g_topk_w[idx];
    g_slot[idx] = pos;
}

// ------------------------- pointwise swiglu ---------------------------------
__global__ void k_swiglu_r() {  // grid Rn
    int r = blockIdx.x;
    float w = g_w[r];
    const float* gp = g_buf + (size_t)r * 2048;
    float* o = g_hr + (size_t)r * In;
    for (int i = threadIdx.x; i < In; i += 256) {
        float gv = gp[i], uv = gp[i + In];
        o[i] = w * (gv / (1.f + expf(-gv))) * uv;
    }
}

__global__ void k_swiglu_s() {  // grid Tn
    int t = blockIdx.x;
    const float* gp = g_buf + (size_t)t * 4096;
    float* o = g_hs + (size_t)t * ISn;
    for (int i = threadIdx.x; i < ISn; i += 256) {
        float gv = gp[i], uv = gp[i + ISn];
        o[i] = (gv / (1.f + expf(-gv))) * uv;
    }
}

// ------------------------- tf32 tensor-core GEMM ----------------------------
// VAR 0: routed up   : gather(x) [grp rows] @ [wg|wu]_e -> g_buf   (K=2048,N=2048)
// VAR 1: routed down : g_hr [grp rows]     @ wd_e       -> g_yr    (K=1024,N=2048)
// VAR 2: shared up   : x                   @ [sg|su]    -> g_buf   (K=2048,N=4096)
// VAR 3: shared down : g_hs                @ sd  (+ yr combine) -> out (K=2048,N=2048)
template <int VAR>
__global__ __launch_bounds__(256)
void gemm_k(const float* __restrict__ A, const float* __restrict__ Ba,
            const float* __restrict__ Bb, float* __restrict__ Cout) {
    constexpr int  KD     = (VAR == 1) ? 1024 : 2048;
    constexpr int  LDA    = (VAR == 1) ? 1024 : 2048;
    constexpr int  LDB    = (VAR == 0) ? 1024 : 2048;
    constexpr int  LDC    = (VAR == 2) ? 4096 : 2048;
    constexpr int  NTH    = (VAR == 0) ? 8 : (VAR == 2) ? 16 : (1 << 30);
    constexpr bool GROUP  = (VAR == 0 || VAR == 1);
    constexpr bool GATHER = (VAR == 0);
    constexpr bool COMB   = (VAR == 3);

    const int tn = blockIdx.x, tm = blockIdx.y, e = blockIdx.z;
    int mcount = Tn, mbase = 0;
    if (GROUP) {
        mcount = g_cnt[e];
        if (tm * 128 >= mcount) return;
        mbase = g_off[e];
    }

    // A source pointer
    const float* Ap;
    if (VAR == 1)      Ap = g_hr;
    else if (VAR == 3) Ap = g_hs;
    else               Ap = A;     // x
    // C destination pointer
    float* Cp;
    if (VAR == 0 || VAR == 2) Cp = g_buf;
    else if (VAR == 1)        Cp = g_yr;
    else                      Cp = Cout;

    // B half-select + expert offset
    const float* Bp; int n0;
    if (tn < NTH) { Bp = Ba; n0 = tn * 128; }
    else          { Bp = Bb; n0 = (tn - NTH) * 128; }
    if (GROUP) Bp += (size_t)e * KD * LDB;

    __shared__ uint32_t As[128 * 36];   // [row][k] pad 36: conflict-free frags
    __shared__ uint32_t Bs[32 * 132];   // [k][n]  pad 132: <=2-way frags

    const int tid  = threadIdx.x;
    const int warp = tid >> 5, lane = tid & 31;
    const int wm = (warp >> 2) * 64, wn = (warp & 3) * 32;
    const int qp = lane >> 2, qr = lane & 3;

    // A staging: 4 rows/thread, 4 k-floats each
    const int akv = (tid & 7) * 4;
    const float* arow[4];
#pragma unroll
    for (int p = 0; p < 4; ++p) {
        int i = (tid >> 3) + 32 * p;
        int lr = tm * 128 + i;
        if (GROUP && lr >= mcount) lr = mcount - 1;
        if (GATHER) arow[p] = Ap + (size_t)g_tok[mbase + lr] * LDA;
        else        arow[p] = Ap + (size_t)(mbase + lr) * LDA;
    }
    // B staging: 4 k-rows/thread, 4 n-floats each
    const int bnv = (tid & 31) * 4;
    const int bkr = tid >> 5;

    float4 ar[4], br[4];
    auto load_stage = [&](int kt) {
#pragma unroll
        for (int p = 0; p < 4; ++p)
            ar[p] = *reinterpret_cast<const float4*>(arow[p] + kt * 32 + akv);
#pragma unroll
        for (int p = 0; p < 4; ++p)
            br[p] = *reinterpret_cast<const float4*>(
                Bp + (size_t)(kt * 32 + bkr + 8 * p) * LDB + n0 + bnv);
    };

    float acc[4][4][4];
#pragma unroll
    for (int i = 0; i < 4; ++i)
#pragma unroll
        for (int j = 0; j < 4; ++j)
#pragma unroll
            for (int k = 0; k < 4; ++k) acc[i][j][k] = 0.f;

    // ldmatrix per-lane address selectors (A fragment: 16x8 tf32)
    const int g8 = lane >> 3, l8 = lane & 7;
    const int a_rsel = ((g8 & 1) ? 8 : 0) + l8;
    const int a_ksel = (g8 >> 1) * 4;
    const uint32_t as_base = (uint32_t)__cvta_generic_to_shared(As);

    load_stage(0);
    constexpr int NIT = KD / 32;
    for (int kt = 0; kt < NIT; ++kt) {
        // store stage -> smem (convert to tf32 with round-to-nearest)
#pragma unroll
        for (int p = 0; p < 4; ++p) {
            int row = (tid >> 3) + 32 * p;
            uint32_t* d = &As[row * 36 + akv];
            d[0] = f2tf(ar[p].x); d[1] = f2tf(ar[p].y);
            d[2] = f2tf(ar[p].z); d[3] = f2tf(ar[p].w);
        }
#pragma unroll
        for (int p = 0; p < 4; ++p) {
            int krow = bkr + 8 * p;
            uint32_t* d = &Bs[krow * 132 + bnv];
            d[0] = f2tf(br[p].x); d[1] = f2tf(br[p].y);
            d[2] = f2tf(br[p].z); d[3] = f2tf(br[p].w);
        }
        __syncthreads();
        if (kt + 1 < NIT) load_stage(kt + 1);  // prefetch overlaps mma below

#pragma unroll
        for (int ks = 0; ks < 4; ++ks) {
            uint32_t afr[4][4];
#pragma unroll
            for (int mi = 0; mi < 4; ++mi) {
                uint32_t ad = as_base +
                    4u * (uint32_t)((wm + mi * 16 + a_rsel) * 36 + ks * 8 + a_ksel);
                ldsm4(afr[mi], ad);
            }
            uint32_t bfr[4][2];
#pragma unroll
            for (int ni = 0; ni < 4; ++ni) {
                int ncol = wn + ni * 8 + qp;
                bfr[ni][0] = Bs[(ks * 8 + qr) * 132 + ncol];
                bfr[ni][1] = Bs[(ks * 8 + qr + 4) * 132 + ncol];
            }
#pragma unroll
            for (int mi = 0; mi < 4; ++mi)
#pragma unroll
                for (int ni = 0; ni < 4; ++ni)
                    mma8(acc[mi][ni], afr[mi], bfr[ni]);
        }
        __syncthreads();
    }

    // epilogue
#pragma unroll
    for (int mi = 0; mi < 4; ++mi) {
        int lr0 = tm * 128 + wm + mi * 16 + qp;
#pragma unroll
        for (int half = 0; half < 2; ++half) {
            int lr = lr0 + half * 8;
            if (GROUP && lr >= mcount) continue;
            size_t rowi = (size_t)(mbase + lr);
#pragma unroll
            for (int ni = 0; ni < 4; ++ni) {
                int nc = tn * 128 + wn + ni * 8 + 2 * qr;
                float2 v;
                v.x = acc[mi][ni][half * 2 + 0];
                v.y = acc[mi][ni][half * 2 + 1];
                if (COMB) {
                    int t = (int)rowi;
                    int s0 = g_slot[2 * t], s1 = g_slot[2 * t + 1];
                    float2 y0 = *reinterpret_cast<const float2*>(&g_yr[(size_t)s0 * Hn + nc]);
                    float2 y1 = *reinterpret_cast<const float2*>(&g_yr[(size_t)s1 * Hn + nc]);
                    v.x += y0.x + y1.x;
                    v.y += y0.y + y1.y;
                }
                *reinterpret_cast<float2*>(&Cp[rowi * LDC + nc]) = v;
            }
        }
    }
}

// ------------------------- launch -------------------------------------------
extern "C" void kernel_launch(void* const* d_in, const int* in_sizes, int n_in,
                              void* d_out, int out_size) {
    (void)in_sizes; (void)n_in; (void)out_size;
    const float* x  = (const float*)d_in[0];
    const float* gw = (const float*)d_in[1];
    const float* wg = (const float*)d_in[2];
    const float* wu = (const float*)d_in[3];
    const float* wd = (const float*)d_in[4];
    const float* sg = (const float*)d_in[5];
    const float* su = (const float*)d_in[6];
    const float* sd = (const float*)d_in[7];
    float* out = (float*)d_out;

    k_zero<<<1, 32>>>();
    k_gate<<<Tn / 8, 256>>>(x, gw);
    k_offsets<<<1, 32>>>();
    k_assign<<<Rn / 256, 256>>>();

    gemm_k<0><<<dim3(16, 16, 8), 256>>>(x, wg, wu, nullptr);   // routed up (gathered)
    k_swiglu_r<<<Rn, 256>>>();                                 // swiglu + weight fold
    gemm_k<1><<<dim3(16, 16, 8), 256>>>(nullptr, wd, nullptr, nullptr);  // routed down
    gemm_k<2><<<dim3(32, 16, 1), 256>>>(x, sg, su, nullptr);   // shared up
    k_swiglu_s<<<Tn, 256>>>();                                 // shared swiglu
    gemm_k<3><<<dim3(16, 16, 1), 256>>>(nullptr, sd, nullptr, out);      // shared down + combine
}

// round 3
// speedup vs baseline: 1.6710x; 1.6710x over previous
#include <cuda_runtime.h>
#include <cuda_fp16.h>
#include <cstdint>
#include <math.h>

constexpr int Tn  = 2048;
constexpr int Hn  = 2048;
constexpr int In  = 1024;
constexpr int En  = 8;
constexpr int ISn = 2048;
constexpr int Rn  = 4096;

// ------------------------- scratch (device globals) -------------------------
__device__ float  g_buf[(size_t)Rn * 2048];   // up-proj outputs f32
__device__ float  g_yr [(size_t)Rn * Hn];     // routed down output f32
__device__ __half c_x  [(size_t)Tn * Hn];     // fp16 activations
__device__ __half c_bu [(size_t)En * Hn * 2048];  // [e][h][wg|wu]
__device__ __half c_wd [(size_t)En * In * Hn];
__device__ __half c_bs [(size_t)Hn * 4096];       // [h][sg|su]
__device__ __half c_sd [(size_t)ISn * Hn];
__device__ __half c_hr [(size_t)Rn * In];     // routed swiglu fp16
__device__ __half c_hs [(size_t)Tn * ISn];    // shared swiglu fp16
__device__ int   g_tok[Rn];
__device__ float g_w  [Rn];
__device__ int   g_slot[Rn];
__device__ int   g_topk_i[Rn];
__device__ float g_topk_w[Rn];
__device__ int   g_cnt[En], g_off[En], g_cnt2[En];

// ------------------------- PTX helpers --------------------------------------
__device__ __forceinline__ uint32_t smem_u32(const void* p) {
    uint32_t a;
    asm("{ .reg .u64 t; cvta.to.shared.u64 t, %1; cvt.u32.u64 %0, t; }" : "=r"(a) : "l"(p));
    return a;
}
__device__ __forceinline__ void cpa16(uint32_t dst, const void* src) {
    asm volatile("cp.async.cg.shared.global [%0], [%1], 16;" :: "r"(dst), "l"(src));
}
__device__ __forceinline__ void ldsm4(uint32_t* d, uint32_t a) {
    asm volatile("ldmatrix.sync.aligned.m8n8.x4.shared.b16 {%0,%1,%2,%3},[%4];"
                 : "=r"(d[0]), "=r"(d[1]), "=r"(d[2]), "=r"(d[3]) : "r"(a));
}
__device__ __forceinline__ void ldsm4t(uint32_t* d, uint32_t a) {
    asm volatile("ldmatrix.sync.aligned.m8n8.x4.trans.shared.b16 {%0,%1,%2,%3},[%4];"
                 : "=r"(d[0]), "=r"(d[1]), "=r"(d[2]), "=r"(d[3]) : "r"(a));
}
__device__ __forceinline__ void mma16(float* c, const uint32_t* a, const uint32_t* b) {
    asm volatile(
        "mma.sync.aligned.m16n8k16.row.col.f32.f16.f16.f32 "
        "{%0,%1,%2,%3},{%4,%5,%6,%7},{%8,%9},{%0,%1,%2,%3};"
        : "+f"(c[0]), "+f"(c[1]), "+f"(c[2]), "+f"(c[3])
        : "r"(a[0]), "r"(a[1]), "r"(a[2]), "r"(a[3]), "r"(b[0]), "r"(b[1]));
}

// ------------------------- gate + routing -----------------------------------
__global__ void k_zero() { if (threadIdx.x < En) g_cnt[threadIdx.x] = 0; }

__global__ void k_gate(const float* __restrict__ x, const float* __restrict__ gw) {
    int warp = threadIdx.x >> 5, lane = threadIdx.x & 31;
    int t = blockIdx.x * 8 + warp;
    float acc[En];
#pragma unroll
    for (int e = 0; e < En; ++e) acc[e] = 0.f;
    const float4* xr = reinterpret_cast<const float4*>(x + (size_t)t * Hn);
#pragma unroll 4
    for (int it = 0; it < Hn / 128; ++it) {
        float4 xv = xr[lane + 32 * it];
#pragma unroll
        for (int e = 0; e < En; ++e) {
            float4 wv = reinterpret_cast<const float4*>(gw + (size_t)e * Hn)[lane + 32 * it];
            acc[e] += xv.x * wv.x + xv.y * wv.y + xv.z * wv.z + xv.w * wv.w;
        }
    }
#pragma unroll
    for (int e = 0; e < En; ++e)
#pragma unroll
        for (int o = 16; o; o >>= 1) acc[e] += __shfl_xor_sync(0xffffffffu, acc[e], o);
    if (lane == 0) {
        int i0 = 0; float l0 = acc[0];
#pragma unroll
        for (int e = 1; e < En; ++e) if (acc[e] > l0) { l0 = acc[e]; i0 = e; }
        int i1 = -1; float l1 = -1e30f;
#pragma unroll
        for (int e = 0; e < En; ++e) if (e != i0 && acc[e] > l1) { l1 = acc[e]; i1 = e; }
        float e1 = expf(l1 - l0);
        float w0 = 1.f / (1.f + e1);
        float w1 = e1 / (1.f + e1);
        g_topk_i[2 * t]     = i0; g_topk_w[2 * t]     = w0;
        g_topk_i[2 * t + 1] = i1; g_topk_w[2 * t + 1] = w1;
        atomicAdd(&g_cnt[i0], 1);
        atomicAdd(&g_cnt[i1], 1);
    }
}

__global__ void k_offsets() {
    if (threadIdx.x == 0) {
        int s = 0;
        for (int e = 0; e < En; ++e) { g_off[e] = s; s += g_cnt[e]; }
    }
    if (threadIdx.x < En) g_cnt2[threadIdx.x] = 0;
}

__global__ void k_assign() {
    int idx = blockIdx.x * 256 + threadIdx.x;
    int e = g_topk_i[idx];
    int pos = g_off[e] + atomicAdd(&g_cnt2[e], 1);
    g_tok[pos] = idx >> 1;
    g_w[pos]   = g_topk_w[idx];
    g_slot[idx] = pos;
}

// ------------------------- f32 -> f16 conversion ----------------------------
__global__ void k_cvt(const float* __restrict__ s, __half* __restrict__ d, int n4) {
    int i = blockIdx.x * 256 + threadIdx.x, stride = gridDim.x * 256;
    for (; i < n4; i += stride) {
        float4 v = reinterpret_cast<const float4*>(s)[i];
        __half2 a = __floats2half2_rn(v.x, v.y);
        __half2 b = __floats2half2_rn(v.z, v.w);
        uint2 o;
        o.x = *reinterpret_cast<uint32_t*>(&a);
        o.y = *reinterpret_cast<uint32_t*>(&b);
        reinterpret_cast<uint2*>(d)[i] = o;
    }
}

// interleave two [rows][inner] f32 tensors into [rows][2*inner] fp16
__global__ void k_cvt_pair(const float* __restrict__ g, const float* __restrict__ u,
                           __half* __restrict__ d, int rows, int inner) {
    int q = blockIdx.x * 256 + threadIdx.x, stride = gridDim.x * 256;
    int i4 = inner / 4;
    int tot = rows * i4;
    for (; q < tot; q += stride) {
        int r = q / i4, c = (q - r * i4) * 4;
        float4 gv = *reinterpret_cast<const float4*>(g + (size_t)r * inner + c);
        float4 uv = *reinterpret_cast<const float4*>(u + (size_t)r * inner + c);
        __half2 a = __floats2half2_rn(gv.x, gv.y), b = __floats2half2_rn(gv.z, gv.w);
        __half2 e = __floats2half2_rn(uv.x, uv.y), f = __floats2half2_rn(uv.z, uv.w);
        uint2 og, ou;
        og.x = *reinterpret_cast<uint32_t*>(&a); og.y = *reinterpret_cast<uint32_t*>(&b);
        ou.x = *reinterpret_cast<uint32_t*>(&e); ou.y = *reinterpret_cast<uint32_t*>(&f);
        *reinterpret_cast<uint2*>(d + (size_t)r * 2 * inner + c) = og;
        *reinterpret_cast<uint2*>(d + (size_t)r * 2 * inner + inner + c) = ou;
    }
}

// ------------------------- pointwise swiglu (fp16 out) ----------------------
__global__ void k_swiglu_r() {   // grid Rn, 256 thr
    int r = blockIdx.x, i = threadIdx.x;
    float w = g_w[r];
    const float4* gp = reinterpret_cast<const float4*>(g_buf + (size_t)r * 2048);
    float4 gv = gp[i], uv = gp[i + 256];
    float o0 = w * (gv.x / (1.f + expf(-gv.x))) * uv.x;
    float o1 = w * (gv.y / (1.f + expf(-gv.y))) * uv.y;
    float o2 = w * (gv.z / (1.f + expf(-gv.z))) * uv.z;
    float o3 = w * (gv.w / (1.f + expf(-gv.w))) * uv.w;
    __half2 a = __floats2half2_rn(o0, o1), b = __floats2half2_rn(o2, o3);
    uint2 o;
    o.x = *reinterpret_cast<uint32_t*>(&a); o.y = *reinterpret_cast<uint32_t*>(&b);
    *reinterpret_cast<uint2*>(c_hr + (size_t)r * In + i * 4) = o;
}
__global__ void k_swiglu_s() {   // grid Tn, 256 thr
    int t = blockIdx.x;
    const float4* gp = reinterpret_cast<const float4*>(g_buf + (size_t)t * 4096);
#pragma unroll
    for (int j = 0; j < 2; ++j) {
        int i = threadIdx.x + j * 256;
        float4 gv = gp[i], uv = gp[i + 512];
        float o0 = (gv.x / (1.f + expf(-gv.x))) * uv.x;
        float o1 = (gv.y / (1.f + expf(-gv.y))) * uv.y;
        float o2 = (gv.z / (1.f + expf(-gv.z))) * uv.z;
        float o3 = (gv.w / (1.f + expf(-gv.w))) * uv.w;
        __half2 a = __floats2half2_rn(o0, o1), b = __floats2half2_rn(o2, o3);
        uint2 o;
        o.x = *reinterpret_cast<uint32_t*>(&a); o.y = *reinterpret_cast<uint32_t*>(&b);
        *reinterpret_cast<uint2*>(c_hs + (size_t)t * ISn + i * 4) = o;
    }
}

// ------------------------- fp16 mma GEMM, cp.async 4-stage ------------------
// Tile 128m x 128n x 32k, 256 threads, warp tile 64x32.
// VAR 0: gather(c_x) @ c_bu[e]  -> g_buf  (K=2048, grouped)
// VAR 1: c_hr        @ c_wd[e]  -> g_yr   (K=1024, grouped)
// VAR 2: c_x         @ c_bs     -> g_buf  (K=2048, LDB/LDC=4096)
// VAR 3: c_hs        @ c_sd     -> out    (K=2048, +combine)
constexpr int ST  = 4;
constexpr int ABY = 128 * 64;    // 8KB per stage (A)
constexpr int BBY = 32 * 256;    // 8KB per stage (B)
constexpr int STG = ABY + BBY;
constexpr int DSM = ST * STG;    // 64KB

template <int VAR>
__global__ __launch_bounds__(256, 2)
void gemm_f16(const __half* __restrict__ Ag, const __half* __restrict__ Bg,
              float* __restrict__ Cg) {
    constexpr int  KD   = (VAR == 1) ? 1024 : 2048;
    constexpr int  LDA  = (VAR == 1) ? 1024 : 2048;
    constexpr int  LDB  = (VAR == 2) ? 4096 : 2048;
    constexpr int  LDC  = (VAR == 2) ? 4096 : 2048;
    constexpr bool GROUP  = (VAR < 2);
    constexpr bool GATHER = (VAR == 0);
    constexpr bool COMB   = (VAR == 3);
    constexpr int  NIT  = KD / 32;

    const int tn = blockIdx.x, tm = blockIdx.y, e = blockIdx.z;
    int mcount = Tn, mbase = 0;
    if (GROUP) {
        mcount = g_cnt[e];
        if (tm * 128 >= mcount) return;
        mbase = g_off[e];
    }
    const __half* Bp = Bg;
    if (VAR == 0) Bp += (size_t)e * Hn * 2048;
    if (VAR == 1) Bp += (size_t)e * In * 2048;
    const int ncol0 = tn * 128;

    extern __shared__ char smraw[];
    const uint32_t smb = smem_u32(smraw);
    const int tid = threadIdx.x;

    // ---- A source: thread owns row tid>>1, two 16B chunks ----
    int lr = tm * 128 + (tid >> 1);
    if (GROUP && lr >= mcount) lr = mcount - 1;
    const __half* arow;
    if (GATHER) arow = Ag + (size_t)g_tok[mbase + lr] * LDA;
    else        arow = Ag + (size_t)(mbase + lr) * LDA;
    const int arq = (tid & 1) * 16;          // halfs offset of first chunk
    arow += arq;
    const int arow_s = tid >> 1;
    const int ac0 = (tid & 1) * 2;
    uint32_t dsta0 = arow_s * 64 + (((ac0)     ^ ((arow_s >> 1) & 3)) << 4);
    uint32_t dsta1 = arow_s * 64 + (((ac0 + 1) ^ ((arow_s >> 1) & 3)) << 4);

    // ---- B source: thread owns k-row tid>>3, two 16B chunks ----
    const int bk = tid >> 3;
    const int bc0 = (tid & 7) * 2;
    const __half* bsrc = Bp + (size_t)bk * LDB + ncol0 + bc0 * 8;
    uint32_t dstb0 = ABY + bk * 256 + (((bc0)     ^ (bk & 7)) << 4);
    uint32_t dstb1 = ABY + bk * 256 + (((bc0 + 1) ^ (bk & 7)) << 4);

    auto load_stage = [&](int sl) {
        uint32_t sb = smb + (sl % ST) * STG;
        const __half* as = arow + sl * 32;
        cpa16(sb + dsta0, as);
        cpa16(sb + dsta1, as + 8);
        const __half* bs = bsrc + (size_t)sl * 32 * LDB;
        cpa16(sb + dstb0, bs);
        cpa16(sb + dstb1, bs + 8);
    };

#pragma unroll
    for (int s = 0; s < ST - 1; ++s) {
        if (s < NIT) load_stage(s);
        asm volatile("cp.async.commit_group;" ::: "memory");
    }

    float acc[4][4][4];
#pragma unroll
    for (int i = 0; i < 4; ++i)
#pragma unroll
        for (int j = 0; j < 4; ++j)
#pragma unroll
            for (int k = 0; k < 4; ++k) acc[i][j][k] = 0.f;

    const int w = tid >> 5, l = tid & 31;
    const int wm = (w >> 2) * 64, wn = (w & 3) * 32;
    const int l15 = l & 15, l16 = l >> 4;

    for (int s = 0; s < NIT; ++s) {
        asm volatile("cp.async.wait_group 2;" ::: "memory");
        __syncthreads();
        {
            int sl = s + ST - 1;
            if (sl < NIT) load_stage(sl);
            asm volatile("cp.async.commit_group;" ::: "memory");
        }
        uint32_t ab = smb + (s % ST) * STG, bb = ab + ABY;
#pragma unroll
        for (int ks = 0; ks < 2; ++ks) {
            uint32_t af[4][4], bf[2][4];
#pragma unroll
            for (int mi = 0; mi < 4; ++mi) {
                int m = wm + mi * 16 + l15;
                int c = ks * 2 + l16;
                ldsm4(af[mi], ab + m * 64 + ((c ^ ((m >> 1) & 3)) << 4));
            }
#pragma unroll
            for (int nj = 0; nj < 2; ++nj) {
                int k = ks * 16 + l15;
                int cn = (wn + nj * 16 + l16 * 8) >> 3;
                ldsm4t(bf[nj], bb + k * 256 + ((cn ^ (k & 7)) << 4));
            }
#pragma unroll
            for (int mi = 0; mi < 4; ++mi)
#pragma unroll
                for (int ni = 0; ni < 4; ++ni)
                    mma16(acc[mi][ni], af[mi], &bf[ni >> 1][(ni & 1) * 2]);
        }
    }

    // ---- epilogue ----
    const int qp = l >> 2, qr = l & 3;
#pragma unroll
    for (int mi = 0; mi < 4; ++mi) {
#pragma unroll
        for (int h = 0; h < 2; ++h) {
            int lrow = tm * 128 + wm + mi * 16 + qp + h * 8;
            if (GROUP && lrow >= mcount) continue;
            size_t rowi = (size_t)(mbase + lrow);
#pragma unroll
            for (int ni = 0; ni < 4; ++ni) {
                int nc = ncol0 + wn + ni * 8 + 2 * qr;
                float2 v;
                v.x = acc[mi][ni][h * 2 + 0];
                v.y = acc[mi][ni][h * 2 + 1];
                if (COMB) {
                    int t = (int)rowi;
                    int s0 = g_slot[2 * t], s1 = g_slot[2 * t + 1];
                    float2 y0 = *reinterpret_cast<const float2*>(&g_yr[(size_t)s0 * Hn + nc]);
                    float2 y1 = *reinterpret_cast<const float2*>(&g_yr[(size_t)s1 * Hn + nc]);
                    v.x += y0.x + y1.x;
                    v.y += y0.y + y1.y;
                }
                *reinterpret_cast<float2*>(&Cg[rowi * LDC + nc]) = v;
            }
        }
    }
}

// ------------------------- launch -------------------------------------------
extern "C" void kernel_launch(void* const* d_in, const int* in_sizes, int n_in,
                              void* d_out, int out_size) {
    (void)in_sizes; (void)n_in; (void)out_size;
    const float* x  = (const float*)d_in[0];
    const float* gw = (const float*)d_in[1];
    const float* wg = (const float*)d_in[2];
    const float* wu = (const float*)d_in[3];
    const float* wd = (const float*)d_in[4];
    const float* sg = (const float*)d_in[5];
    const float* su = (const float*)d_in[6];
    const float* sd = (const float*)d_in[7];
    float* out = (float*)d_out;

    cudaFuncSetAttribute(gemm_f16<0>, cudaFuncAttributeMaxDynamicSharedMemorySize, DSM);
    cudaFuncSetAttribute(gemm_f16<1>, cudaFuncAttributeMaxDynamicSharedMemorySize, DSM);
    cudaFuncSetAttribute(gemm_f16<2>, cudaFuncAttributeMaxDynamicSharedMemorySize, DSM);
    cudaFuncSetAttribute(gemm_f16<3>, cudaFuncAttributeMaxDynamicSharedMemorySize, DSM);

    __half *p_cx, *p_cbu, *p_cwd, *p_cbs, *p_csd;
    float *p_gbuf, *p_gyr;
    cudaGetSymbolAddress((void**)&p_cx,  c_x);
    cudaGetSymbolAddress((void**)&p_cbu, c_bu);
    cudaGetSymbolAddress((void**)&p_cwd, c_wd);
    cudaGetSymbolAddress((void**)&p_cbs, c_bs);
    cudaGetSymbolAddress((void**)&p_csd, c_sd);
    cudaGetSymbolAddress((void**)&p_gbuf, g_buf);
    cudaGetSymbolAddress((void**)&p_gyr,  g_yr);
    __half *p_chr, *p_chs;
    cudaGetSymbolAddress((void**)&p_chr, c_hr);
    cudaGetSymbolAddress((void**)&p_chs, c_hs);

    // routing
    k_zero<<<1, 32>>>();
    k_gate<<<Tn / 8, 256>>>(x, gw);
    k_offsets<<<1, 32>>>();
    k_assign<<<Rn / 256, 256>>>();

    // fp16 conversion
    k_cvt<<<1024, 256>>>(x,  p_cx,  Tn * Hn / 4);
    k_cvt_pair<<<2048, 256>>>(wg, wu, p_cbu, En * Hn, In);
    k_cvt<<<2048, 256>>>(wd, p_cwd, En * In * Hn / 4);
    k_cvt_pair<<<1024, 256>>>(sg, su, p_cbs, Hn, ISn);
    k_cvt<<<1024, 256>>>(sd, p_csd, ISn * Hn / 4);

    // GEMM chain
    gemm_f16<0><<<dim3(16, 32, 8), 256, DSM>>>(p_cx,  p_cbu, p_gbuf);
    k_swiglu_r<<<Rn, 256>>>();
    gemm_f16<1><<<dim3(16, 32, 8), 256, DSM>>>(p_chr, p_cwd, p_gyr);
    gemm_f16<2><<<dim3(32, 16, 1), 256, DSM>>>(p_cx,  p_cbs, p_gbuf);
    k_swiglu_s<<<Tn, 256>>>();
    gemm_f16<3><<<dim3(16, 16, 1), 256, DSM>>>(p_chs, p_csd, out);
}

// round 4
// speedup vs baseline: 1.7797x; 1.0650x over previous
#include <cuda_runtime.h>
#include <cuda_fp16.h>
#include <cstdint>
#include <math.h>

constexpr int Tn  = 2048;
constexpr int Hn  = 2048;
constexpr int In  = 1024;
constexpr int En  = 8;
constexpr int ISn = 2048;
constexpr int Rn  = 4096;

// ------------------------- scratch (device globals) -------------------------
__device__ float  g_yr [(size_t)Rn * Hn];         // routed down output f32
__device__ __half c_x  [(size_t)Tn * Hn];         // fp16 activations
__device__ __half c_bu [(size_t)En * Hn * 2048];  // [e][h][(g,u) interleaved]
__device__ __half c_wd [(size_t)En * In * Hn];
__device__ __half c_bs [(size_t)Hn * 4096];       // [h][(g,u) interleaved]
__device__ __half c_sd [(size_t)ISn * Hn];
__device__ __half c_hr [(size_t)Rn * In];         // routed swiglu fp16 (weight folded)
__device__ __half c_hs [(size_t)Tn * ISn];        // shared swiglu fp16
__device__ int   g_tok[Rn];
__device__ float g_w  [Rn];
__device__ int   g_slot[Rn];
__device__ int   g_topk_i[Rn];
__device__ float g_topk_w[Rn];
__device__ int   g_cnt[En], g_off[En], g_cnt2[En];

// ------------------------- PTX helpers --------------------------------------
__device__ __forceinline__ uint32_t smem_u32(const void* p) {
    uint32_t a;
    asm("{ .reg .u64 t; cvta.to.shared.u64 t, %1; cvt.u32.u64 %0, t; }" : "=r"(a) : "l"(p));
    return a;
}
__device__ __forceinline__ void cpa16(uint32_t dst, const void* src) {
    asm volatile("cp.async.cg.shared.global [%0], [%1], 16;" :: "r"(dst), "l"(src));
}
__device__ __forceinline__ void ldsm4(uint32_t* d, uint32_t a) {
    asm volatile("ldmatrix.sync.aligned.m8n8.x4.shared.b16 {%0,%1,%2,%3},[%4];"
                 : "=r"(d[0]), "=r"(d[1]), "=r"(d[2]), "=r"(d[3]) : "r"(a));
}
__device__ __forceinline__ void ldsm4t(uint32_t* d, uint32_t a) {
    asm volatile("ldmatrix.sync.aligned.m8n8.x4.trans.shared.b16 {%0,%1,%2,%3},[%4];"
                 : "=r"(d[0]), "=r"(d[1]), "=r"(d[2]), "=r"(d[3]) : "r"(a));
}
__device__ __forceinline__ void mma16(float* c, const uint32_t* a, const uint32_t* b) {
    asm volatile(
        "mma.sync.aligned.m16n8k16.row.col.f32.f16.f16.f32 "
        "{%0,%1,%2,%3},{%4,%5,%6,%7},{%8,%9},{%0,%1,%2,%3};"
        : "+f"(c[0]), "+f"(c[1]), "+f"(c[2]), "+f"(c[3])
        : "r"(a[0]), "r"(a[1]), "r"(a[2]), "r"(a[3]), "r"(b[0]), "r"(b[1]));
}

// ------------------------- gate + routing (+ x->fp16) -----------------------
__global__ void k_zero() { if (threadIdx.x < En) g_cnt[threadIdx.x] = 0; }

__global__ void k_gate(const float* __restrict__ x, const float* __restrict__ gw) {
    int warp = threadIdx.x >> 5, lane = threadIdx.x & 31;
    int t = blockIdx.x * 8 + warp;
    float acc[En];
#pragma unroll
    for (int e = 0; e < En; ++e) acc[e] = 0.f;
    const float4* xr = reinterpret_cast<const float4*>(x + (size_t)t * Hn);
    uint2* xo = reinterpret_cast<uint2*>(c_x + (size_t)t * Hn);
#pragma unroll 4
    for (int it = 0; it < Hn / 128; ++it) {
        float4 xv = xr[lane + 32 * it];
        __half2 h0 = __floats2half2_rn(xv.x, xv.y);
        __half2 h1 = __floats2half2_rn(xv.z, xv.w);
        uint2 ov;
        ov.x = *reinterpret_cast<uint32_t*>(&h0);
        ov.y = *reinterpret_cast<uint32_t*>(&h1);
        xo[lane + 32 * it] = ov;
#pragma unroll
        for (int e = 0; e < En; ++e) {
            float4 wv = reinterpret_cast<const float4*>(gw + (size_t)e * Hn)[lane + 32 * it];
            acc[e] += xv.x * wv.x + xv.y * wv.y + xv.z * wv.z + xv.w * wv.w;
        }
    }
#pragma unroll
    for (int e = 0; e < En; ++e)
#pragma unroll
        for (int o = 16; o; o >>= 1) acc[e] += __shfl_xor_sync(0xffffffffu, acc[e], o);
    if (lane == 0) {
        int i0 = 0; float l0 = acc[0];
#pragma unroll
        for (int e = 1; e < En; ++e) if (acc[e] > l0) { l0 = acc[e]; i0 = e; }
        int i1 = -1; float l1 = -1e30f;
#pragma unroll
        for (int e = 0; e < En; ++e) if (e != i0 && acc[e] > l1) { l1 = acc[e]; i1 = e; }
        float e1 = expf(l1 - l0);
        float w0 = 1.f / (1.f + e1);
        float w1 = e1 / (1.f + e1);
        g_topk_i[2 * t]     = i0; g_topk_w[2 * t]     = w0;
        g_topk_i[2 * t + 1] = i1; g_topk_w[2 * t + 1] = w1;
        atomicAdd(&g_cnt[i0], 1);
        atomicAdd(&g_cnt[i1], 1);
    }
}

__global__ void k_offsets() {
    if (threadIdx.x == 0) {
        int s = 0;
        for (int e = 0; e < En; ++e) { g_off[e] = s; s += g_cnt[e]; }
    }
    if (threadIdx.x < En) g_cnt2[threadIdx.x] = 0;
}

__global__ void k_assign() {
    int idx = blockIdx.x * 256 + threadIdx.x;
    int e = g_topk_i[idx];
    int pos = g_off[e] + atomicAdd(&g_cnt2[e], 1);
    g_tok[pos] = idx >> 1;
    g_w[pos]   = g_topk_w[idx];
    g_slot[idx] = pos;
}

// ------------------------- merged weight conversion -------------------------
// pair-interleave: d[r][2c+0]=g[r][c], d[r][2c+1]=u[r][c]
__device__ __forceinline__ void cvt_pair_seg(const float* g, const float* u,
                                             __half* d, int rows, int inner,
                                             int gid, int gstride) {
    int i4 = inner / 4, tot = rows * i4;
    for (int q = gid; q < tot; q += gstride) {
        int r = q / i4, c = (q - r * i4) * 4;
        float4 gv = *reinterpret_cast<const float4*>(g + (size_t)r * inner + c);
        float4 uv = *reinterpret_cast<const float4*>(u + (size_t)r * inner + c);
        __half2 p0 = __floats2half2_rn(gv.x, uv.x);
        __half2 p1 = __floats2half2_rn(gv.y, uv.y);
        __half2 p2 = __floats2half2_rn(gv.z, uv.z);
        __half2 p3 = __floats2half2_rn(gv.w, uv.w);
        uint4 o;
        o.x = *reinterpret_cast<uint32_t*>(&p0);
        o.y = *reinterpret_cast<uint32_t*>(&p1);
        o.z = *reinterpret_cast<uint32_t*>(&p2);
        o.w = *reinterpret_cast<uint32_t*>(&p3);
        *reinterpret_cast<uint4*>(d + (size_t)r * 2 * inner + 2 * c) = o;
    }
}
__device__ __forceinline__ void cvt_seg(const float* s, __half* d, int n4,
                                        int gid, int gstride) {
    for (int i = gid; i < n4; i += gstride) {
        float4 v = reinterpret_cast<const float4*>(s)[i];
        __half2 a = __floats2half2_rn(v.x, v.y);
        __half2 b = __floats2half2_rn(v.z, v.w);
        uint2 o;
        o.x = *reinterpret_cast<uint32_t*>(&a);
        o.y = *reinterpret_cast<uint32_t*>(&b);
        reinterpret_cast<uint2*>(d)[i] = o;
    }
}
__global__ void k_cvt_all(const float* __restrict__ wg, const float* __restrict__ wu,
                          const float* __restrict__ wd, const float* __restrict__ sg,
                          const float* __restrict__ su, const float* __restrict__ sd) {
    int gid = blockIdx.x * 256 + threadIdx.x, gs = gridDim.x * 256;
    cvt_pair_seg(wg, wu, c_bu, En * Hn, In, gid, gs);
    cvt_pair_seg(sg, su, c_bs, Hn, ISn, gid, gs);
    cvt_seg(wd, c_wd, En * In * Hn / 4, gid, gs);
    cvt_seg(sd, c_sd, ISn * Hn / 4, gid, gs);
}

// ------------------------- fp16 mma GEMM, cp.async 4-stage ------------------
// Tile 128m x 128n x 32k, 256 threads, warp tile 64x32.
// VAR 0: gather(c_x) @ c_bu[e] -> swiglu(+w) -> c_hr     (K=2048, grouped)
// VAR 1: c_hr        @ c_wd[e] -> g_yr                   (K=1024, grouped)
// VAR 2: c_x         @ c_bs    -> swiglu -> c_hs         (K=2048, LDB=4096)
// VAR 3: c_hs        @ c_sd    -> out (+routed combine)  (K=2048)
constexpr int ST  = 4;
constexpr int ABY = 128 * 64;
constexpr int BBY = 32 * 256;
constexpr int STG = ABY + BBY;
constexpr int DSM = ST * STG;    // 64KB

template <int VAR>
__global__ __launch_bounds__(256, 2)
void gemm_f16(const __half* __restrict__ Ag, const __half* __restrict__ Bg,
              float* __restrict__ Cg, __half* __restrict__ Ch) {
    constexpr int  KD   = (VAR == 1) ? 1024 : 2048;
    constexpr int  LDA  = (VAR == 1) ? 1024 : 2048;
    constexpr int  LDB  = (VAR == 2) ? 4096 : 2048;
    constexpr int  LDC  = 2048;
    constexpr int  LDO  = (VAR == 0) ? 1024 : 2048;   // swiglu fp16 out ld
    constexpr bool GROUP  = (VAR < 2);
    constexpr bool GATHER = (VAR == 0);
    constexpr bool COMB   = (VAR == 3);
    constexpr bool SWI    = (VAR == 0 || VAR == 2);
    constexpr int  NIT  = KD / 32;

    const int tn = blockIdx.x, tm = blockIdx.y, e = blockIdx.z;
    int mcount = Tn, mbase = 0;
    if (GROUP) {
        mcount = g_cnt[e];
        if (tm * 128 >= mcount) return;
        mbase = g_off[e];
    }
    const __half* Bp = Bg;
    if (VAR == 0) Bp += (size_t)e * Hn * 2048;
    if (VAR == 1) Bp += (size_t)e * In * 2048;
    const int ncol0 = tn * 128;

    extern __shared__ char smraw[];
    const uint32_t smb = smem_u32(smraw);
    const int tid = threadIdx.x;

    // ---- A source ----
    int lr = tm * 128 + (tid >> 1);
    if (GROUP && lr >= mcount) lr = mcount - 1;
    const __half* arow;
    if (GATHER) arow = Ag + (size_t)g_tok[mbase + lr] * LDA;
    else        arow = Ag + (size_t)(mbase + lr) * LDA;
    arow += (tid & 1) * 16;
    const int arow_s = tid >> 1;
    const int ac0 = (tid & 1) * 2;
    uint32_t dsta0 = arow_s * 64 + (((ac0)     ^ ((arow_s >> 1) & 3)) << 4);
    uint32_t dsta1 = arow_s * 64 + (((ac0 + 1) ^ ((arow_s >> 1) & 3)) << 4);

    // ---- B source ----
    const int bk = tid >> 3;
    const int bc0 = (tid & 7) * 2;
    const __half* bsrc = Bp + (size_t)bk * LDB + ncol0 + bc0 * 8;
    uint32_t dstb0 = ABY + bk * 256 + (((bc0)     ^ (bk & 7)) << 4);
    uint32_t dstb1 = ABY + bk * 256 + (((bc0 + 1) ^ (bk & 7)) << 4);

    auto load_stage = [&](int sl) {
        uint32_t sb = smb + (sl % ST) * STG;
        const __half* as = arow + sl * 32;
        cpa16(sb + dsta0, as);
        cpa16(sb + dsta1, as + 8);
        const __half* bs = bsrc + (size_t)sl * 32 * LDB;
        cpa16(sb + dstb0, bs);
        cpa16(sb + dstb1, bs + 8);
    };

#pragma unroll
    for (int s = 0; s < ST - 1; ++s) {
        if (s < NIT) load_stage(s);
        asm volatile("cp.async.commit_group;" ::: "memory");
    }

    float acc[4][4][4];
#pragma unroll
    for (int i = 0; i < 4; ++i)
#pragma unroll
        for (int j = 0; j < 4; ++j)
#pragma unroll
            for (int k = 0; k < 4; ++k) acc[i][j][k] = 0.f;

    const int w = tid >> 5, l = tid & 31;
    const int wm = (w >> 2) * 64, wn = (w & 3) * 32;
    const int l15 = l & 15, l16 = l >> 4;

    for (int s = 0; s < NIT; ++s) {
        asm volatile("cp.async.wait_group 2;" ::: "memory");
        __syncthreads();
        {
            int sl = s + ST - 1;
            if (sl < NIT) load_stage(sl);
            asm volatile("cp.async.commit_group;" ::: "memory");
        }
        uint32_t ab = smb + (s % ST) * STG, bb = ab + ABY;
#pragma unroll
        for (int ks = 0; ks < 2; ++ks) {
            uint32_t af[4][4], bf[2][4];
#pragma unroll
            for (int mi = 0; mi < 4; ++mi) {
                int m = wm + mi * 16 + l15;
                int c = ks * 2 + l16;
                ldsm4(af[mi], ab + m * 64 + ((c ^ ((m >> 1) & 3)) << 4));
            }
#pragma unroll
            for (int nj = 0; nj < 2; ++nj) {
                int k = ks * 16 + l15;
                int cn = (wn + nj * 16 + l16 * 8) >> 3;
                ldsm4t(bf[nj], bb + k * 256 + ((cn ^ (k & 7)) << 4));
            }
#pragma unroll
            for (int mi = 0; mi < 4; ++mi)
#pragma unroll
                for (int ni = 0; ni < 4; ++ni)
                    mma16(acc[mi][ni], af[mi], &bf[ni >> 1][(ni & 1) * 2]);
        }
    }

    const int qp = l >> 2, qr = l & 3;

    if (SWI) {
        // ---- swiglu epilogue: pairs (g,u) in adjacent cols; stage fp16 in smem ----
        __syncthreads();
        __half* sm = reinterpret_cast<__half*>(smraw);   // [128][72] padded
#pragma unroll
        for (int mi = 0; mi < 4; ++mi) {
#pragma unroll
            for (int h = 0; h < 2; ++h) {
                int row = wm + mi * 16 + qp + h * 8;
                float wgt = 1.f;
                if (GROUP) {
                    int cr = tm * 128 + row;
                    if (cr >= mcount) cr = mcount - 1;
                    wgt = g_w[mbase + cr];
                }
#pragma unroll
                for (int ni = 0; ni < 4; ++ni) {
                    int pi = (wn >> 1) + ni * 4 + qr;
                    float gv = acc[mi][ni][h * 2 + 0];
                    float uv = acc[mi][ni][h * 2 + 1];
                    float o = wgt * (gv / (1.f + expf(-gv))) * uv;
                    sm[row * 72 + pi] = __float2half_rn(o);
                }
            }
        }
        __syncthreads();
        // coalesced writeout: 2 threads per row, 32 halfs each
        int row = tid >> 1;
        int lrow = tm * 128 + row;
        if (!GROUP || lrow < mcount) {
            size_t rowi = (size_t)(mbase + lrow);
            const uint4* src = reinterpret_cast<const uint4*>(sm + row * 72 + (tid & 1) * 32);
            uint4* dst = reinterpret_cast<uint4*>(Ch + rowi * LDO + tn * 64 + (tid & 1) * 32);
#pragma unroll
            for (int q = 0; q < 4; ++q) dst[q] = src[q];
        }
        return;
    }

    // ---- f32 epilogue (VAR 1 and 3) ----
#pragma unroll
    for (int mi = 0; mi < 4; ++mi) {
#pragma unroll
        for (int h = 0; h < 2; ++h) {
            int lrow = tm * 128 + wm + mi * 16 + qp + h * 8;
            if (GROUP && lrow >= mcount) continue;
            size_t rowi = (size_t)(mbase + lrow);
#pragma unroll
            for (int ni = 0; ni < 4; ++ni) {
                int nc = ncol0 + wn + ni * 8 + 2 * qr;
                float2 v;
                v.x = acc[mi][ni][h * 2 + 0];
                v.y = acc[mi][ni][h * 2 + 1];
                if (COMB) {
                    int t = (int)rowi;
                    int s0 = g_slot[2 * t], s1 = g_slot[2 * t + 1];
                    float2 y0 = *reinterpret_cast<const float2*>(&g_yr[(size_t)s0 * Hn + nc]);
                    float2 y1 = *reinterpret_cast<const float2*>(&g_yr[(size_t)s1 * Hn + nc]);
                    v.x += y0.x + y1.x;
                    v.y += y0.y + y1.y;
                }
                *reinterpret_cast<float2*>(&Cg[rowi * LDC + nc]) = v;
            }
        }
    }
}

// ------------------------- launch -------------------------------------------
extern "C" void kernel_launch(void* const* d_in, const int* in_sizes, int n_in,
                              void* d_out, int out_size) {
    (void)in_sizes; (void)n_in; (void)out_size;
    const float* x  = (const float*)d_in[0];
    const float* gw = (const float*)d_in[1];
    const float* wg = (const float*)d_in[2];
    const float* wu = (const float*)d_in[3];
    const float* wd = (const float*)d_in[4];
    const float* sg = (const float*)d_in[5];
    const float* su = (const float*)d_in[6];
    const float* sd = (const float*)d_in[7];
    float* out = (float*)d_out;

    cudaFuncSetAttribute(gemm_f16<0>, cudaFuncAttributeMaxDynamicSharedMemorySize, DSM);
    cudaFuncSetAttribute(gemm_f16<1>, cudaFuncAttributeMaxDynamicSharedMemorySize, DSM);
    cudaFuncSetAttribute(gemm_f16<2>, cudaFuncAttributeMaxDynamicSharedMemorySize, DSM);
    cudaFuncSetAttribute(gemm_f16<3>, cudaFuncAttributeMaxDynamicSharedMemorySize, DSM);

    __half *p_cx, *p_cbu, *p_cwd, *p_cbs, *p_csd, *p_chr, *p_chs;
    float *p_gyr;
    cudaGetSymbolAddress((void**)&p_cx,  c_x);
    cudaGetSymbolAddress((void**)&p_cbu, c_bu);
    cudaGetSymbolAddress((void**)&p_cwd, c_wd);
    cudaGetSymbolAddress((void**)&p_cbs, c_bs);
    cudaGetSymbolAddress((void**)&p_csd, c_sd);
    cudaGetSymbolAddress((void**)&p_chr, c_hr);
    cudaGetSymbolAddress((void**)&p_chs, c_hs);
    cudaGetSymbolAddress((void**)&p_gyr, g_yr);

    k_zero<<<1, 32>>>();
    k_gate<<<Tn / 8, 256>>>(x, gw);                    // gate + x->fp16
    k_offsets<<<1, 32>>>();
    k_assign<<<Rn / 256, 256>>>();
    k_cvt_all<<<2048, 256>>>(wg, wu, wd, sg, su, sd);  // all weights, one launch

    gemm_f16<0><<<dim3(16, 32, 8), 256, DSM>>>(p_cx,  p_cbu, nullptr, p_chr);  // up+swiglu
    gemm_f16<1><<<dim3(16, 32, 8), 256, DSM>>>(p_chr, p_cwd, p_gyr, nullptr);  // routed down
    gemm_f16<2><<<dim3(32, 16, 1), 256, DSM>>>(p_cx,  p_cbs, nullptr, p_chs);  // shared up+swiglu
    gemm_f16<3><<<dim3(16, 16, 1), 256, DSM>>>(p_chs, p_csd, out, nullptr);    // down + combine
}

// round 7
// speedup vs baseline: 1.7861x; 1.0036x over previous
#include <cuda_runtime.h>
#include <cuda_fp16.h>
#include <cstdint>
#include <math.h>

constexpr int Tn  = 2048;
constexpr int Hn  = 2048;
constexpr int In  = 1024;
constexpr int En  = 8;
constexpr int ISn = 2048;
constexpr int Rn  = 4096;

// ------------------------- scratch (device globals) -------------------------
__device__ float  g_yr [(size_t)Rn * Hn];
__device__ __half c_x  [(size_t)Tn * Hn];
__device__ __half c_bu [(size_t)En * Hn * 2048];  // [e][h][(g,u) interleaved]
__device__ __half c_wd [(size_t)En * In * Hn];
__device__ __half c_bs [(size_t)Hn * 4096];       // [h][(g,u) interleaved]
__device__ __half c_sd [(size_t)ISn * Hn];
__device__ __half c_hr [(size_t)Rn * In];
__device__ __half c_hs [(size_t)Tn * ISn];
__device__ int   g_tok[Rn];
__device__ float g_w  [Rn];
__device__ int   g_slot[Rn];
__device__ int   g_topk_i[Rn];
__device__ float g_topk_w[Rn];
__device__ int   g_cnt[En], g_off[En], g_cnt2[En];

// ------------------------- PTX helpers --------------------------------------
__device__ __forceinline__ uint32_t smem_u32(const void* p) {
    uint32_t a;
    asm("{ .reg .u64 t; cvta.to.shared.u64 t, %1; cvt.u32.u64 %0, t; }" : "=r"(a) : "l"(p));
    return a;
}
__device__ __forceinline__ void cpa16(uint32_t dst, const void* src) {
    asm volatile("cp.async.cg.shared.global [%0], [%1], 16;" :: "r"(dst), "l"(src));
}
__device__ __forceinline__ void ldsm4(uint32_t* d, uint32_t a) {
    asm volatile("ldmatrix.sync.aligned.m8n8.x4.shared.b16 {%0,%1,%2,%3},[%4];"
                 : "=r"(d[0]), "=r"(d[1]), "=r"(d[2]), "=r"(d[3]) : "r"(a));
}
__device__ __forceinline__ void ldsm4t(uint32_t* d, uint32_t a) {
    asm volatile("ldmatrix.sync.aligned.m8n8.x4.trans.shared.b16 {%0,%1,%2,%3},[%4];"
                 : "=r"(d[0]), "=r"(d[1]), "=r"(d[2]), "=r"(d[3]) : "r"(a));
}
__device__ __forceinline__ void mma16(float* c, const uint32_t* a, const uint32_t* b) {
    asm volatile(
        "mma.sync.aligned.m16n8k16.row.col.f32.f16.f16.f32 "
        "{%0,%1,%2,%3},{%4,%5,%6,%7},{%8,%9},{%0,%1,%2,%3};"
        : "+f"(c[0]), "+f"(c[1]), "+f"(c[2]), "+f"(c[3])
        : "r"(a[0]), "r"(a[1]), "r"(a[2]), "r"(a[3]), "r"(b[0]), "r"(b[1]));
}

// ------------------------- gate + routing (+ x->fp16) -----------------------
__global__ void k_zero() { if (threadIdx.x < En) g_cnt[threadIdx.x] = 0; }

__global__ void k_gate(const float* __restrict__ x, const float* __restrict__ gw) {
    int warp = threadIdx.x >> 5, lane = threadIdx.x & 31;
    int t = blockIdx.x * 8 + warp;
    float acc[En];
#pragma unroll
    for (int e = 0; e < En; ++e) acc[e] = 0.f;
    const float4* xr = reinterpret_cast<const float4*>(x + (size_t)t * Hn);
    uint2* xo = reinterpret_cast<uint2*>(c_x + (size_t)t * Hn);
#pragma unroll 4
    for (int it = 0; it < Hn / 128; ++it) {
        float4 xv = xr[lane + 32 * it];
        __half2 h0 = __floats2half2_rn(xv.x, xv.y);
        __half2 h1 = __floats2half2_rn(xv.z, xv.w);
        uint2 ov;
        ov.x = *reinterpret_cast<uint32_t*>(&h0);
        ov.y = *reinterpret_cast<uint32_t*>(&h1);
        xo[lane + 32 * it] = ov;
#pragma unroll
        for (int e = 0; e < En; ++e) {
            float4 wv = reinterpret_cast<const float4*>(gw + (size_t)e * Hn)[lane + 32 * it];
            acc[e] += xv.x * wv.x + xv.y * wv.y + xv.z * wv.z + xv.w * wv.w;
        }
    }
#pragma unroll
    for (int e = 0; e < En; ++e)
#pragma unroll
        for (int o = 16; o; o >>= 1) acc[e] += __shfl_xor_sync(0xffffffffu, acc[e], o);
    if (lane == 0) {
        int i0 = 0; float l0 = acc[0];
#pragma unroll
        for (int e = 1; e < En; ++e) if (acc[e] > l0) { l0 = acc[e]; i0 = e; }
        int i1 = -1; float l1 = -1e30f;
#pragma unroll
        for (int e = 0; e < En; ++e) if (e != i0 && acc[e] > l1) { l1 = acc[e]; i1 = e; }
        float e1 = expf(l1 - l0);
        float w0 = 1.f / (1.f + e1);
        float w1 = e1 / (1.f + e1);
        g_topk_i[2 * t]     = i0; g_topk_w[2 * t]     = w0;
        g_topk_i[2 * t + 1] = i1; g_topk_w[2 * t + 1] = w1;
        atomicAdd(&g_cnt[i0], 1);
        atomicAdd(&g_cnt[i1], 1);
    }
}

__global__ void k_offsets() {
    if (threadIdx.x == 0) {
        int s = 0;
        for (int e = 0; e < En; ++e) { g_off[e] = s; s += g_cnt[e]; }
    }
    if (threadIdx.x < En) g_cnt2[threadIdx.x] = 0;
}

__global__ void k_assign() {
    int idx = blockIdx.x * 256 + threadIdx.x;
    int e = g_topk_i[idx];
    int pos = g_off[e] + atomicAdd(&g_cnt2[e], 1);
    g_tok[pos] = idx >> 1;
    g_w[pos]   = g_topk_w[idx];
    g_slot[idx] = pos;
}

// ------------------------- weight conversion ---------------------------------
__device__ __forceinline__ void cvt_pair_seg(const float* g, const float* u,
                                             __half* d, int rows, int inner,
                                             int gid, int gstride) {
    int i4 = inner / 4, tot = rows * i4;
    for (int q = gid; q < tot; q += gstride) {
        int r = q / i4, c = (q - r * i4) * 4;
        float4 gv = *reinterpret_cast<const float4*>(g + (size_t)r * inner + c);
        float4 uv = *reinterpret_cast<const float4*>(u + (size_t)r * inner + c);
        __half2 p0 = __floats2half2_rn(gv.x, uv.x);
        __half2 p1 = __floats2half2_rn(gv.y, uv.y);
        __half2 p2 = __floats2half2_rn(gv.z, uv.z);
        __half2 p3 = __floats2half2_rn(gv.w, uv.w);
        uint4 o;
        o.x = *reinterpret_cast<uint32_t*>(&p0);
        o.y = *reinterpret_cast<uint32_t*>(&p1);
        o.z = *reinterpret_cast<uint32_t*>(&p2);
        o.w = *reinterpret_cast<uint32_t*>(&p3);
        *reinterpret_cast<uint4*>(d + (size_t)r * 2 * inner + 2 * c) = o;
    }
}
__device__ __forceinline__ void cvt_seg(const float* s, __half* d, int n4,
                                        int gid, int gstride) {
    for (int i = gid; i < n4; i += gstride) {
        float4 v = reinterpret_cast<const float4*>(s)[i];
        __half2 a = __floats2half2_rn(v.x, v.y);
        __half2 b = __floats2half2_rn(v.z, v.w);
        uint2 o;
        o.x = *reinterpret_cast<uint32_t*>(&a);
        o.y = *reinterpret_cast<uint32_t*>(&b);
        reinterpret_cast<uint2*>(d)[i] = o;
    }
}
__global__ void k_cvt_bu(const float* __restrict__ wg, const float* __restrict__ wu) {
    int gid = blockIdx.x * 256 + threadIdx.x, gs = gridDim.x * 256;
    cvt_pair_seg(wg, wu, c_bu, En * Hn, In, gid, gs);
}
__global__ void k_cvt_rest(const float* __restrict__ wd, const float* __restrict__ sg,
                           const float* __restrict__ su, const float* __restrict__ sd) {
    int gid = blockIdx.x * 256 + threadIdx.x, gs = gridDim.x * 256;
    cvt_seg(wd, c_wd, En * In * Hn / 4, gid, gs);
    cvt_pair_seg(sg, su, c_bs, Hn, ISn, gid, gs);
    cvt_seg(sd, c_sd, ISn * Hn / 4, gid, gs);
}

// ------------------------- fp16 mma GEMM (R4-proven): 128x128x32, warp 64x32 -
constexpr int ST  = 4;
constexpr int ABY = 128 * 64;
constexpr int BBY = 32 * 256;
constexpr int STG = ABY + BBY;
constexpr int DSM = ST * STG;    // 64KB

template <int VAR>
__global__ __launch_bounds__(256, 2)
void gemm_f16(const __half* __restrict__ Ag, const __half* __restrict__ Bg,
              float* __restrict__ Cg, __half* __restrict__ Ch) {
    constexpr int  KD   = (VAR == 1) ? 1024 : 2048;
    constexpr int  LDA  = (VAR == 1) ? 1024 : 2048;
    constexpr int  LDB  = (VAR == 2) ? 4096 : 2048;
    constexpr int  LDC  = 2048;
    constexpr int  LDO  = (VAR == 0) ? 1024 : 2048;
    constexpr bool GROUP  = (VAR < 2);
    constexpr bool GATHER = (VAR == 0);
    constexpr bool COMB   = (VAR == 3);
    constexpr bool SWI    = (VAR == 0 || VAR == 2);
    constexpr int  NIT  = KD / 32;

    const int tn = blockIdx.x, tm = blockIdx.y, e = blockIdx.z;
    int mcount = Tn, mbase = 0;
    if (GROUP) {
        mcount = g_cnt[e];
        if (tm * 128 >= mcount) return;
        mbase = g_off[e];
    }
    const __half* Bp = Bg;
    if (VAR == 0) Bp += (size_t)e * Hn * 2048;
    if (VAR == 1) Bp += (size_t)e * In * 2048;
    const int ncol0 = tn * 128;

    extern __shared__ char smraw[];
    const uint32_t smb = smem_u32(smraw);
    const int tid = threadIdx.x;

    // ---- A source ----
    int lr = tm * 128 + (tid >> 1);
    if (GROUP && lr >= mcount) lr = mcount - 1;
    const __half* arow;
    if (GATHER) arow = Ag + (size_t)g_tok[mbase + lr] * LDA;
    else        arow = Ag + (size_t)(mbase + lr) * LDA;
    arow += (tid & 1) * 16;
    const int arow_s = tid >> 1;
    const int ac0 = (tid & 1) * 2;
    uint32_t dsta0 = arow_s * 64 + (((ac0)     ^ ((arow_s >> 1) & 3)) << 4);
    uint32_t dsta1 = arow_s * 64 + (((ac0 + 1) ^ ((arow_s >> 1) & 3)) << 4);

    // ---- B source ----
    const int bk = tid >> 3;
    const int bc0 = (tid & 7) * 2;
    const __half* bsrc = Bp + (size_t)bk * LDB + ncol0 + bc0 * 8;
    uint32_t dstb0 = ABY + bk * 256 + (((bc0)     ^ (bk & 7)) << 4);
    uint32_t dstb1 = ABY + bk * 256 + (((bc0 + 1) ^ (bk & 7)) << 4);

    auto load_stage = [&](int sl) {
        uint32_t sb = smb + (sl % ST) * STG;
        const __half* as = arow + sl * 32;
        cpa16(sb + dsta0, as);
        cpa16(sb + dsta1, as + 8);
        const __half* bs = bsrc + (size_t)sl * 32 * LDB;
        cpa16(sb + dstb0, bs);
        cpa16(sb + dstb1, bs + 8);
    };

#pragma unroll
    for (int s = 0; s < ST - 1; ++s) {
        if (s < NIT) load_stage(s);
        asm volatile("cp.async.commit_group;" ::: "memory");
    }

    float acc[4][4][4];
#pragma unroll
    for (int i = 0; i < 4; ++i)
#pragma unroll
        for (int j = 0; j < 4; ++j)
#pragma unroll
            for (int k = 0; k < 4; ++k) acc[i][j][k] = 0.f;

    const int w = tid >> 5, l = tid & 31;
    const int wm = (w >> 2) * 64, wn = (w & 3) * 32;
    const int l15 = l & 15, l16 = l >> 4;

    for (int s = 0; s < NIT; ++s) {
        asm volatile("cp.async.wait_group 2;" ::: "memory");
        __syncthreads();
        {
            int sl = s + ST - 1;
            if (sl < NIT) load_stage(sl);
            asm volatile("cp.async.commit_group;" ::: "memory");
        }
        uint32_t ab = smb + (s % ST) * STG, bb = ab + ABY;
#pragma unroll
        for (int ks = 0; ks < 2; ++ks) {
            uint32_t af[4][4], bf[2][4];
#pragma unroll
            for (int mi = 0; mi < 4; ++mi) {
                int m = wm + mi * 16 + l15;
                int c = ks * 2 + l16;
                ldsm4(af[mi], ab + m * 64 + ((c ^ ((m >> 1) & 3)) << 4));
            }
#pragma unroll
            for (int nj = 0; nj < 2; ++nj) {
                int k = ks * 16 + l15;
                int cn = (wn + nj * 16 + l16 * 8) >> 3;
                ldsm4t(bf[nj], bb + k * 256 + ((cn ^ (k & 7)) << 4));
            }
#pragma unroll
            for (int mi = 0; mi < 4; ++mi)
#pragma unroll
                for (int ni = 0; ni < 4; ++ni)
                    mma16(acc[mi][ni], af[mi], &bf[ni >> 1][(ni & 1) * 2]);
        }
    }

    const int qp = l >> 2, qr = l & 3;

    if (SWI) {
        // ---- swiglu epilogue: (g,u) adjacent cols; fp16 staged in smem ----
        __syncthreads();
        __half* sm = reinterpret_cast<__half*>(smraw);   // [128][72]
#pragma unroll
        for (int mi = 0; mi < 4; ++mi) {
#pragma unroll
            for (int h = 0; h < 2; ++h) {
                int row = wm + mi * 16 + qp + h * 8;
                float wgt = 1.f;
                if (GROUP) {
                    int cr = tm * 128 + row;
                    if (cr >= mcount) cr = mcount - 1;
                    wgt = g_w[mbase + cr];
                }
#pragma unroll
                for (int ni = 0; ni < 4; ++ni) {
                    int pi = (wn >> 1) + ni * 4 + qr;
                    float gv = acc[mi][ni][h * 2 + 0];
                    float uv = acc[mi][ni][h * 2 + 1];
                    float o = wgt * (gv / (1.f + expf(-gv))) * uv;
                    sm[row * 72 + pi] = __float2half_rn(o);
                }
            }
        }
        __syncthreads();
        // coalesced writeout: 2 threads per row, 32 halfs each
        int row = tid >> 1;
        int lrow = tm * 128 + row;
        if (!GROUP || lrow < mcount) {
            size_t rowi = (size_t)(mbase + lrow);
            const uint4* src = reinterpret_cast<const uint4*>(sm + row * 72 + (tid & 1) * 32);
            uint4* dst = reinterpret_cast<uint4*>(Ch + rowi * LDO + tn * 64 + (tid & 1) * 32);
#pragma unroll
            for (int q = 0; q < 4; ++q) dst[q] = src[q];
        }
        return;
    }

    // ---- f32 epilogue (VAR 1 and 3) ----
#pragma unroll
    for (int mi = 0; mi < 4; ++mi) {
#pragma unroll
        for (int h = 0; h < 2; ++h) {
            int lrow = tm * 128 + wm + mi * 16 + qp + h * 8;
            if (GROUP && lrow >= mcount) continue;
            size_t rowi = (size_t)(mbase + lrow);
#pragma unroll
            for (int ni = 0; ni < 4; ++ni) {
                int nc = ncol0 + wn + ni * 8 + 2 * qr;
                float2 v;
                v.x = acc[mi][ni][h * 2 + 0];
                v.y = acc[mi][ni][h * 2 + 1];
                if (COMB) {
                    int t = (int)rowi;
                    int s0 = g_slot[2 * t], s1 = g_slot[2 * t + 1];
                    float2 y0 = *reinterpret_cast<const float2*>(&g_yr[(size_t)s0 * Hn + nc]);
                    float2 y1 = *reinterpret_cast<const float2*>(&g_yr[(size_t)s1 * Hn + nc]);
                    v.x += y0.x + y1.x;
                    v.y += y0.y + y1.y;
                }
                *reinterpret_cast<float2*>(&Cg[rowi * LDC + nc]) = v;
            }
        }
    }
}

// ------------------------- launch -------------------------------------------
extern "C" void kernel_launch(void* const* d_in, const int* in_sizes, int n_in,
                              void* d_out, int out_size) {
    (void)in_sizes; (void)n_in; (void)out_size;
    const float* x  = (const float*)d_in[0];
    const float* gw = (const float*)d_in[1];
    const float* wg = (const float*)d_in[2];
    const float* wu = (const float*)d_in[3];
    const float* wd = (const float*)d_in[4];
    const float* sg = (const float*)d_in[5];
    const float* su = (const float*)d_in[6];
    const float* sd = (const float*)d_in[7];
    float* out = (float*)d_out;

    cudaFuncSetAttribute(gemm_f16<0>, cudaFuncAttributeMaxDynamicSharedMemorySize, DSM);
    cudaFuncSetAttribute(gemm_f16<1>, cudaFuncAttributeMaxDynamicSharedMemorySize, DSM);
    cudaFuncSetAttribute(gemm_f16<2>, cudaFuncAttributeMaxDynamicSharedMemorySize, DSM);
    cudaFuncSetAttribute(gemm_f16<3>, cudaFuncAttributeMaxDynamicSharedMemorySize, DSM);

    __half *p_cx, *p_cbu, *p_cwd, *p_cbs, *p_csd, *p_chr, *p_chs;
    float *p_gyr;
    cudaGetSymbolAddress((void**)&p_cx,  c_x);
    cudaGetSymbolAddress((void**)&p_cbu, c_bu);
    cudaGetSymbolAddress((void**)&p_cwd, c_wd);
    cudaGetSymbolAddress((void**)&p_cbs, c_bs);
    cudaGetSymbolAddress((void**)&p_csd, c_sd);
    cudaGetSymbolAddress((void**)&p_chr, c_hr);
    cudaGetSymbolAddress((void**)&p_chs, c_hs);
    cudaGetSymbolAddress((void**)&p_gyr, g_yr);

    // Fork/join: weight conversions on a side stream, overlapping gate/routing
    // and the (tensor-bound) first GEMM. Falls back to serial if setup fails.
    cudaStream_t s2 = 0;
    cudaEvent_t evFork = 0, evBu = 0, evRest = 0;
    bool forked =
        (cudaStreamCreateWithFlags(&s2, cudaStreamNonBlocking) == cudaSuccess) &&
        (cudaEventCreateWithFlags(&evFork, cudaEventDisableTiming) == cudaSuccess) &&
        (cudaEventCreateWithFlags(&evBu,   cudaEventDisableTiming) == cudaSuccess) &&
        (cudaEventCreateWithFlags(&evRest, cudaEventDisableTiming) == cudaSuccess);

    if (forked) {
        cudaEventRecord(evFork, 0);
        cudaStreamWaitEvent(s2, evFork, 0);
        k_cvt_bu<<<2048, 256, 0, s2>>>(wg, wu);
        cudaEventRecord(evBu, s2);
        k_cvt_rest<<<2048, 256, 0, s2>>>(wd, sg, su, sd);
        cudaEventRecord(evRest, s2);
    }

    k_zero<<<1, 32>>>();
    k_gate<<<Tn / 8, 256>>>(x, gw);
    k_offsets<<<1, 32>>>();
    k_assign<<<Rn / 256, 256>>>();

    if (!forked) {
        k_cvt_bu<<<2048, 256>>>(wg, wu);
        k_cvt_rest<<<2048, 256>>>(wd, sg, su, sd);
    } else {
        cudaStreamWaitEvent(0, evBu, 0);
    }

    gemm_f16<0><<<dim3(16, 32, 8), 256, DSM>>>(p_cx, p_cbu, nullptr, p_chr);   // routed up+swiglu

    if (forked) cudaStreamWaitEvent(0, evRest, 0);

    gemm_f16<1><<<dim3(16, 32, 8), 256, DSM>>>(p_chr, p_cwd, p_gyr, nullptr);  // routed down
    gemm_f16<2><<<dim3(32, 16, 1), 256, DSM>>>(p_cx, p_cbs, nullptr, p_chs);   // shared up+swiglu
    gemm_f16<3><<<dim3(16, 16, 1), 256, DSM>>>(p_chs, p_csd, out, nullptr);    // shared down+combine
}

// round 8
// speedup vs baseline: 1.7877x; 1.0009x over previous
#include <cuda_runtime.h>
#include <cuda_fp16.h>
#include <cstdint>
#include <math.h>

constexpr int Tn  = 2048;
constexpr int Hn  = 2048;
constexpr int In  = 1024;
constexpr int En  = 8;
constexpr int ISn = 2048;
constexpr int Rn  = 4096;

// ------------------------- scratch (device globals) -------------------------
__device__ float  g_yr [(size_t)Rn * Hn];
__device__ __half c_x  [(size_t)Tn * Hn];
__device__ __half c_bu [(size_t)En * Hn * 2048];  // [e][h][(g,u) interleaved]
__device__ __half c_wd [(size_t)En * In * Hn];
__device__ __half c_bs [(size_t)Hn * 4096];       // [h][(g,u) interleaved]
__device__ __half c_sd [(size_t)ISn * Hn];
__device__ __half c_hr [(size_t)Rn * In];
__device__ __half c_hs [(size_t)Tn * ISn];
__device__ int   g_tok[Rn];
__device__ float g_w  [Rn];
__device__ int   g_slot[Rn];
__device__ int   g_topk_i[Rn];
__device__ float g_topk_w[Rn];
__device__ int   g_cnt[En], g_off[En];

// ------------------------- PTX helpers --------------------------------------
__device__ __forceinline__ uint32_t smem_u32(const void* p) {
    uint32_t a;
    asm("{ .reg .u64 t; cvta.to.shared.u64 t, %1; cvt.u32.u64 %0, t; }" : "=r"(a) : "l"(p));
    return a;
}
__device__ __forceinline__ void cpa16(uint32_t dst, const void* src) {
    asm volatile("cp.async.cg.shared.global [%0], [%1], 16;" :: "r"(dst), "l"(src));
}
__device__ __forceinline__ void ldsm4(uint32_t* d, uint32_t a) {
    asm volatile("ldmatrix.sync.aligned.m8n8.x4.shared.b16 {%0,%1,%2,%3},[%4];"
                 : "=r"(d[0]), "=r"(d[1]), "=r"(d[2]), "=r"(d[3]) : "r"(a));
}
__device__ __forceinline__ void ldsm4t(uint32_t* d, uint32_t a) {
    asm volatile("ldmatrix.sync.aligned.m8n8.x4.trans.shared.b16 {%0,%1,%2,%3},[%4];"
                 : "=r"(d[0]), "=r"(d[1]), "=r"(d[2]), "=r"(d[3]) : "r"(a));
}
__device__ __forceinline__ void mma16(float* c, const uint32_t* a, const uint32_t* b) {
    asm volatile(
        "mma.sync.aligned.m16n8k16.row.col.f32.f16.f16.f32 "
        "{%0,%1,%2,%3},{%4,%5,%6,%7},{%8,%9},{%0,%1,%2,%3};"
        : "+f"(c[0]), "+f"(c[1]), "+f"(c[2]), "+f"(c[3])
        : "r"(a[0]), "r"(a[1]), "r"(a[2]), "r"(a[3]), "r"(b[0]), "r"(b[1]));
}

// ------------------------- gate (+ x->fp16) ----------------------------------
__global__ void k_gate(const float* __restrict__ x, const float* __restrict__ gw) {
    int warp = threadIdx.x >> 5, lane = threadIdx.x & 31;
    int t = blockIdx.x * 8 + warp;
    float acc[En];
#pragma unroll
    for (int e = 0; e < En; ++e) acc[e] = 0.f;
    const float4* xr = reinterpret_cast<const float4*>(x + (size_t)t * Hn);
    uint2* xo = reinterpret_cast<uint2*>(c_x + (size_t)t * Hn);
#pragma unroll 4
    for (int it = 0; it < Hn / 128; ++it) {
        float4 xv = xr[lane + 32 * it];
        __half2 h0 = __floats2half2_rn(xv.x, xv.y);
        __half2 h1 = __floats2half2_rn(xv.z, xv.w);
        uint2 ov;
        ov.x = *reinterpret_cast<uint32_t*>(&h0);
        ov.y = *reinterpret_cast<uint32_t*>(&h1);
        xo[lane + 32 * it] = ov;
#pragma unroll
        for (int e = 0; e < En; ++e) {
            float4 wv = reinterpret_cast<const float4*>(gw + (size_t)e * Hn)[lane + 32 * it];
            acc[e] += xv.x * wv.x + xv.y * wv.y + xv.z * wv.z + xv.w * wv.w;
        }
    }
#pragma unroll
    for (int e = 0; e < En; ++e)
#pragma unroll
        for (int o = 16; o; o >>= 1) acc[e] += __shfl_xor_sync(0xffffffffu, acc[e], o);
    if (lane == 0) {
        int i0 = 0; float l0 = acc[0];
#pragma unroll
        for (int e = 1; e < En; ++e) if (acc[e] > l0) { l0 = acc[e]; i0 = e; }
        int i1 = -1; float l1 = -1e30f;
#pragma unroll
        for (int e = 0; e < En; ++e) if (e != i0 && acc[e] > l1) { l1 = acc[e]; i1 = e; }
        float e1 = expf(l1 - l0);
        float w0 = 1.f / (1.f + e1);
        float w1 = e1 / (1.f + e1);
        g_topk_i[2 * t]     = i0; g_topk_w[2 * t]     = w0;
        g_topk_i[2 * t + 1] = i1; g_topk_w[2 * t + 1] = w1;
    }
}

// ------------------------- fused routing (single CTA) ------------------------
__global__ void k_route() {
    __shared__ int cnt[En], off[En], cur[En];
    int tid = threadIdx.x;
    if (tid < En) cnt[tid] = 0;
    __syncthreads();
    for (int i = tid; i < Rn; i += 256) atomicAdd(&cnt[g_topk_i[i]], 1);
    __syncthreads();
    if (tid == 0) {
        int s = 0;
        for (int e = 0; e < En; ++e) { off[e] = s; s += cnt[e]; }
    }
    __syncthreads();
    if (tid < En) { g_cnt[tid] = cnt[tid]; g_off[tid] = off[tid]; cur[tid] = 0; }
    __syncthreads();
    for (int i = tid; i < Rn; i += 256) {
        int e = g_topk_i[i];
        int pos = off[e] + atomicAdd(&cur[e], 1);
        g_tok[pos] = i >> 1;
        g_w[pos]   = g_topk_w[i];
        g_slot[i]  = pos;
    }
}

// ------------------------- weight conversion ---------------------------------
__device__ __forceinline__ void cvt_pair_seg(const float* g, const float* u,
                                             __half* d, int rows, int inner,
                                             int gid, int gstride) {
    int i4 = inner / 4, tot = rows * i4;
    for (int q = gid; q < tot; q += gstride) {
        int r = q / i4, c = (q - r * i4) * 4;
        float4 gv = *reinterpret_cast<const float4*>(g + (size_t)r * inner + c);
        float4 uv = *reinterpret_cast<const float4*>(u + (size_t)r * inner + c);
        __half2 p0 = __floats2half2_rn(gv.x, uv.x);
        __half2 p1 = __floats2half2_rn(gv.y, uv.y);
        __half2 p2 = __floats2half2_rn(gv.z, uv.z);
        __half2 p3 = __floats2half2_rn(gv.w, uv.w);
        uint4 o;
        o.x = *reinterpret_cast<uint32_t*>(&p0);
        o.y = *reinterpret_cast<uint32_t*>(&p1);
        o.z = *reinterpret_cast<uint32_t*>(&p2);
        o.w = *reinterpret_cast<uint32_t*>(&p3);
        *reinterpret_cast<uint4*>(d + (size_t)r * 2 * inner + 2 * c) = o;
    }
}
__device__ __forceinline__ void cvt_seg(const float* s, __half* d, int n4,
                                        int gid, int gstride) {
    for (int i = gid; i < n4; i += gstride) {
        float4 v = reinterpret_cast<const float4*>(s)[i];
        __half2 a = __floats2half2_rn(v.x, v.y);
        __half2 b = __floats2half2_rn(v.z, v.w);
        uint2 o;
        o.x = *reinterpret_cast<uint32_t*>(&a);
        o.y = *reinterpret_cast<uint32_t*>(&b);
        reinterpret_cast<uint2*>(d)[i] = o;
    }
}
__global__ void k_cvt_bu(const float* __restrict__ wg, const float* __restrict__ wu) {
    int gid = blockIdx.x * 256 + threadIdx.x, gs = gridDim.x * 256;
    cvt_pair_seg(wg, wu, c_bu, En * Hn, In, gid, gs);
}
__global__ void k_cvt_rest(const float* __restrict__ wd, const float* __restrict__ sg,
                           const float* __restrict__ su, const float* __restrict__ sd) {
    int gid = blockIdx.x * 256 + threadIdx.x, gs = gridDim.x * 256;
    cvt_seg(wd, c_wd, En * In * Hn / 4, gid, gs);
    cvt_pair_seg(sg, su, c_bs, Hn, ISn, gid, gs);
    cvt_seg(sd, c_sd, ISn * Hn / 4, gid, gs);
}

// ------------------------- fp16 mma GEMM (R4-proven): 128x128x32, warp 64x32 -
constexpr int ST  = 4;
constexpr int ABY = 128 * 64;
constexpr int BBY = 32 * 256;
constexpr int STG = ABY + BBY;
constexpr int DSM = ST * STG;    // 64KB

template <int VAR>
__global__ __launch_bounds__(256, 2)
void gemm_f16(const __half* __restrict__ Ag, const __half* __restrict__ Bg,
              float* __restrict__ Cg, __half* __restrict__ Ch) {
    constexpr int  KD   = (VAR == 1) ? 1024 : 2048;
    constexpr int  LDA  = (VAR == 1) ? 1024 : 2048;
    constexpr int  LDB  = (VAR == 2) ? 4096 : 2048;
    constexpr int  LDC  = 2048;
    constexpr int  LDO  = (VAR == 0) ? 1024 : 2048;
    constexpr bool GROUP  = (VAR < 2);
    constexpr bool GATHER = (VAR == 0);
    constexpr bool COMB   = (VAR == 3);
    constexpr bool SWI    = (VAR == 0 || VAR == 2);
    constexpr int  NIT  = KD / 32;

    const int tn = blockIdx.x, tm = blockIdx.y, e = blockIdx.z;
    int mcount = Tn, mbase = 0;
    if (GROUP) {
        mcount = g_cnt[e];
        if (tm * 128 >= mcount) return;
        mbase = g_off[e];
    }
    const __half* Bp = Bg;
    if (VAR == 0) Bp += (size_t)e * Hn * 2048;
    if (VAR == 1) Bp += (size_t)e * In * 2048;
    const int ncol0 = tn * 128;

    extern __shared__ char smraw[];
    const uint32_t smb = smem_u32(smraw);
    const int tid = threadIdx.x;

    // ---- A source ----
    int lr = tm * 128 + (tid >> 1);
    if (GROUP && lr >= mcount) lr = mcount - 1;
    const __half* arow;
    if (GATHER) arow = Ag + (size_t)g_tok[mbase + lr] * LDA;
    else        arow = Ag + (size_t)(mbase + lr) * LDA;
    arow += (tid & 1) * 16;
    const int arow_s = tid >> 1;
    const int ac0 = (tid & 1) * 2;
    uint32_t dsta0 = arow_s * 64 + (((ac0)     ^ ((arow_s >> 1) & 3)) << 4);
    uint32_t dsta1 = arow_s * 64 + (((ac0 + 1) ^ ((arow_s >> 1) & 3)) << 4);

    // ---- B source ----
    const int bk = tid >> 3;
    const int bc0 = (tid & 7) * 2;
    const __half* bsrc = Bp + (size_t)bk * LDB + ncol0 + bc0 * 8;
    uint32_t dstb0 = ABY + bk * 256 + (((bc0)     ^ (bk & 7)) << 4);
    uint32_t dstb1 = ABY + bk * 256 + (((bc0 + 1) ^ (bk & 7)) << 4);

    auto load_stage = [&](int sl) {
        uint32_t sb = smb + (sl % ST) * STG;
        const __half* as = arow + sl * 32;
        cpa16(sb + dsta0, as);
        cpa16(sb + dsta1, as + 8);
        const __half* bs = bsrc + (size_t)sl * 32 * LDB;
        cpa16(sb + dstb0, bs);
        cpa16(sb + dstb1, bs + 8);
    };

#pragma unroll
    for (int s = 0; s < ST - 1; ++s) {
        if (s < NIT) load_stage(s);
        asm volatile("cp.async.commit_group;" ::: "memory");
    }

    float acc[4][4][4];
#pragma unroll
    for (int i = 0; i < 4; ++i)
#pragma unroll
        for (int j = 0; j < 4; ++j)
#pragma unroll
            for (int k = 0; k < 4; ++k) acc[i][j][k] = 0.f;

    const int w = tid >> 5, l = tid & 31;
    const int wm = (w >> 2) * 64, wn = (w & 3) * 32;
    const int l15 = l & 15, l16 = l >> 4;

    for (int s = 0; s < NIT; ++s) {
        asm volatile("cp.async.wait_group 2;" ::: "memory");
        __syncthreads();
        {
            int sl = s + ST - 1;
            if (sl < NIT) load_stage(sl);
            asm volatile("cp.async.commit_group;" ::: "memory");
        }
        uint32_t ab = smb + (s % ST) * STG, bb = ab + ABY;
#pragma unroll
        for (int ks = 0; ks < 2; ++ks) {
            uint32_t af[4][4], bf[2][4];
#pragma unroll
            for (int mi = 0; mi < 4; ++mi) {
                int m = wm + mi * 16 + l15;
                int c = ks * 2 + l16;
                ldsm4(af[mi], ab + m * 64 + ((c ^ ((m >> 1) & 3)) << 4));
            }
#pragma unroll
            for (int nj = 0; nj < 2; ++nj) {
                int k = ks * 16 + l15;
                int cn = (wn + nj * 16 + l16 * 8) >> 3;
                ldsm4t(bf[nj], bb + k * 256 + ((cn ^ (k & 7)) << 4));
            }
#pragma unroll
            for (int mi = 0; mi < 4; ++mi)
#pragma unroll
                for (int ni = 0; ni < 4; ++ni)
                    mma16(acc[mi][ni], af[mi], &bf[ni >> 1][(ni & 1) * 2]);
        }
    }

    const int qp = l >> 2, qr = l & 3;

    if (SWI) {
        // ---- swiglu epilogue: (g,u) adjacent cols; fp16 staged in smem ----
        __syncthreads();
        __half* sm = reinterpret_cast<__half*>(smraw);   // [128][72]
#pragma unroll
        for (int mi = 0; mi < 4; ++mi) {
#pragma unroll
            for (int h = 0; h < 2; ++h) {
                int row = wm + mi * 16 + qp + h * 8;
                float wgt = 1.f;
                if (GROUP) {
                    int cr = tm * 128 + row;
                    if (cr >= mcount) cr = mcount - 1;
                    wgt = g_w[mbase + cr];
                }
#pragma unroll
                for (int ni = 0; ni < 4; ++ni) {
                    int pi = (wn >> 1) + ni * 4 + qr;
                    float gv = acc[mi][ni][h * 2 + 0];
                    float uv = acc[mi][ni][h * 2 + 1];
                    float o = wgt * (gv / (1.f + expf(-gv))) * uv;
                    sm[row * 72 + pi] = __float2half_rn(o);
                }
            }
        }
        __syncthreads();
        int row = tid >> 1;
        int lrow = tm * 128 + row;
        if (!GROUP || lrow < mcount) {
            size_t rowi = (size_t)(mbase + lrow);
            const uint4* src = reinterpret_cast<const uint4*>(sm + row * 72 + (tid & 1) * 32);
            uint4* dst = reinterpret_cast<uint4*>(Ch + rowi * LDO + tn * 64 + (tid & 1) * 32);
#pragma unroll
            for (int q = 0; q < 4; ++q) dst[q] = src[q];
        }
        return;
    }

    // ---- f32 epilogue (VAR 1 and 3) ----
#pragma unroll
    for (int mi = 0; mi < 4; ++mi) {
#pragma unroll
        for (int h = 0; h < 2; ++h) {
            int lrow = tm * 128 + wm + mi * 16 + qp + h * 8;
            if (GROUP && lrow >= mcount) continue;
            size_t rowi = (size_t)(mbase + lrow);
#pragma unroll
            for (int ni = 0; ni < 4; ++ni) {
                int nc = ncol0 + wn + ni * 8 + 2 * qr;
                float2 v;
                v.x = acc[mi][ni][h * 2 + 0];
                v.y = acc[mi][ni][h * 2 + 1];
                if (COMB) {
                    int t = (int)rowi;
                    int s0 = g_slot[2 * t], s1 = g_slot[2 * t + 1];
                    float2 y0 = *reinterpret_cast<const float2*>(&g_yr[(size_t)s0 * Hn + nc]);
                    float2 y1 = *reinterpret_cast<const float2*>(&g_yr[(size_t)s1 * Hn + nc]);
                    v.x += y0.x + y1.x;
                    v.y += y0.y + y1.y;
                }
                *reinterpret_cast<float2*>(&Cg[rowi * LDC + nc]) = v;
            }
        }
    }
}

// ------------------------- launch -------------------------------------------
extern "C" void kernel_launch(void* const* d_in, const int* in_sizes, int n_in,
                              void* d_out, int out_size) {
    (void)in_sizes; (void)n_in; (void)out_size;
    const float* x  = (const float*)d_in[0];
    const float* gw = (const float*)d_in[1];
    const float* wg = (const float*)d_in[2];
    const float* wu = (const float*)d_in[3];
    const float* wd = (const float*)d_in[4];
    const float* sg = (const float*)d_in[5];
    const float* su = (const float*)d_in[6];
    const float* sd = (const float*)d_in[7];
    float* out = (float*)d_out;

    cudaFuncSetAttribute(gemm_f16<0>, cudaFuncAttributeMaxDynamicSharedMemorySize, DSM);
    cudaFuncSetAttribute(gemm_f16<1>, cudaFuncAttributeMaxDynamicSharedMemorySize, DSM);
    cudaFuncSetAttribute(gemm_f16<2>, cudaFuncAttributeMaxDynamicSharedMemorySize, DSM);
    cudaFuncSetAttribute(gemm_f16<3>, cudaFuncAttributeMaxDynamicSharedMemorySize, DSM);

    __half *p_cx, *p_cbu, *p_cwd, *p_cbs, *p_csd, *p_chr, *p_chs;
    float *p_gyr;
    cudaGetSymbolAddress((void**)&p_cx,  c_x);
    cudaGetSymbolAddress((void**)&p_cbu, c_bu);
    cudaGetSymbolAddress((void**)&p_cwd, c_wd);
    cudaGetSymbolAddress((void**)&p_cbs, c_bs);
    cudaGetSymbolAddress((void**)&p_csd, c_sd);
    cudaGetSymbolAddress((void**)&p_chr, c_hr);
    cudaGetSymbolAddress((void**)&p_chs, c_hs);
    cudaGetSymbolAddress((void**)&p_gyr, g_yr);

    // Launch order puts gemm_f16<0> in the profiler's slot (4th launch).
    k_gate<<<Tn / 8, 256>>>(x, gw);                                            // 1
    k_route<<<1, 256>>>();                                                     // 2
    k_cvt_bu<<<2048, 256>>>(wg, wu);                                           // 3
    gemm_f16<0><<<dim3(16, 32, 8), 256, DSM>>>(p_cx, p_cbu, nullptr, p_chr);   // 4 (profiled)
    k_cvt_rest<<<2048, 256>>>(wd, sg, su, sd);                                 // 5
    gemm_f16<1><<<dim3(16, 32, 8), 256, DSM>>>(p_chr, p_cwd, p_gyr, nullptr);  // 6
    gemm_f16<2><<<dim3(32, 16, 1), 256, DSM>>>(p_cx, p_cbs, nullptr, p_chs);   // 7
    gemm_f16<3><<<dim3(16, 16, 1), 256, DSM>>>(p_chs, p_csd, out, nullptr);    // 8
}